// round 11
// baseline (speedup 1.0000x reference)
#include <cuda_runtime.h>
#include <cuda_bf16.h>
#include <cstdint>

// Problem: x (1024,64), D (64,256), w (256). Output (1024,2) fp32.
#define NN 1024
#define MM 256
#define DN 64
#define LAMBD 0.2f
#define EPS 1e-5f
#define KKT_MARGIN 1e-3f
#define MAX_SWEEPS 64
#define MAXS 64

// ---------------- device scratch ----------------
__device__ float    g_G[MM * MM];      // fp32 Gram D^T D, row-major
__device__ unsigned g_Gp[MM * 128];    // packed bf16x2: word[j*128+t] = (G[j][t], G[j][t+128])

// ---------------- K1: G = D^T D, fused bf16x2 pack ----------------
__global__ void gram_pack_kernel(const float* __restrict__ D) {
    __shared__ float Dj[DN];
    __shared__ float row[MM];
    int j = blockIdx.x, k = threadIdx.x;
    if (k < DN) Dj[k] = D[k * MM + j];
    __syncthreads();
    float acc = 0.f;
#pragma unroll 8
    for (int n = 0; n < DN; ++n) acc = fmaf(Dj[n], D[n * MM + k], acc);
    g_G[j * MM + k] = acc;
    row[k] = acc;
    __syncthreads();
    if (k < 128) {
        unsigned u0 = (unsigned)__bfloat16_as_ushort(__float2bfloat16(row[k]));
        unsigned u1 = (unsigned)__bfloat16_as_ushort(__float2bfloat16(row[k + 128]));
        g_Gp[j * 128 + k] = u0 | (u1 << 16);
    }
}

// ---------------- K2: fused b=D^Tx -> CD (one ballot per batch visit, one-touch drain)
//                  -> fp32 residual refresh -> KKT filter -> warp Cholesky refine ----------------
// 128 blocks x 256 threads. Warp per sample. Lane l owns coords
// j(ai) = ((ai>>2)<<7) + ((ai&3)<<5) + l, ai = 0..7.
// Dynamic smem: 128KB bf16x2 G; after CD reused as 8 x 16KB per-warp Cholesky scratch.
#define CD_SMEM (MM * 128 * 4)

__global__ void __launch_bounds__(256, 1) main_kernel(const float* __restrict__ x,
                                                      const float* __restrict__ D,
                                                      const float* __restrict__ w,
                                                      float* __restrict__ out) {
    extern __shared__ unsigned Gs[];         // 32768 words bf16x2 G, later refine scratch
    __shared__ float s_b[8][MM];             // b per warp
    __shared__ float s_r[8][MM];             // refreshed residual u per warp (KKT + signs)
    __shared__ int   s_idx[8][MAXS];
    __shared__ float s_vec[8][MAXS];

    // cooperative load of packed G
    {
        const uint4* src = (const uint4*)g_Gp;
        uint4* dst = (uint4*)Gs;
        for (int t = threadIdx.x; t < (MM * 128) / 4; t += 256) dst[t] = src[t];
    }

    int warp = threadIdx.x >> 5, lane = threadIdx.x & 31;
    int s = blockIdx.x * 8 + warp;

    // ---- prologue: b = D^T x_s, register accumulators ----
    float x0 = x[s * DN + lane];
    float x1 = x[s * DN + 32 + lane];
    float uu[8], zz[8];
#pragma unroll
    for (int ai = 0; ai < 8; ++ai) { uu[ai] = 0.f; zz[ai] = 0.f; }
#pragma unroll 4
    for (int n = 0; n < 32; ++n) {
        float xs = __shfl_sync(0xffffffffu, x0, n);
        const float* dr = D + n * MM + lane;
#pragma unroll
        for (int ai = 0; ai < 8; ++ai)
            uu[ai] = fmaf(xs, dr[((ai >> 2) << 7) + ((ai & 3) << 5)], uu[ai]);
    }
#pragma unroll 4
    for (int n = 0; n < 32; ++n) {
        float xs = __shfl_sync(0xffffffffu, x1, n);
        const float* dr = D + (n + 32) * MM + lane;
#pragma unroll
        for (int ai = 0; ai < 8; ++ai)
            uu[ai] = fmaf(xs, dr[((ai >> 2) << 7) + ((ai & 3) << 5)], uu[ai]);
    }
#pragma unroll
    for (int ai = 0; ai < 8; ++ai)
        s_b[warp][((ai >> 2) << 7) + ((ai & 3) << 5) + lane] = uu[ai];

    __syncthreads();   // G smem ready

    // ---- CD: one ballot per batch visit; drain each set bit ONCE with fresh
    //      recompute + broadcast + conditional apply; then next batch ----
    for (int sweep = 0; sweep < MAX_SWEEPS; ++sweep) {
        unsigned any = 0;
#pragma unroll
        for (int ai = 0; ai < 8; ++ai) {
            int jbase = ((ai >> 2) << 7) + ((ai & 3) << 5);
            float c = uu[ai] + zz[ai];
            float ab = fabsf(c) - LAMBD;
            float cand = ab > 0.f ? copysignf(ab, c) : 0.f;
            unsigned chg = __ballot_sync(0xffffffffu, fabsf(cand - zz[ai]) > EPS);
            if (!chg) continue;
            any = 1;
            do {
                int l0 = __ffs(chg) - 1;
                chg &= chg - 1;
                // hoist G-row loads (addresses depend only on l0; overlap LDS w/ chain)
                const unsigned* grow = Gs + ((jbase + l0) << 7) + lane;
                unsigned g0 = grow[0], g1 = grow[32], g2 = grow[64], g3 = grow[96];
                // fresh candidate (uu may have moved since the ballot)
                float c2 = uu[ai] + zz[ai];
                float ab2 = fabsf(c2) - LAMBD;
                float cand2 = ab2 > 0.f ? copysignf(ab2, c2) : 0.f;
                float d2 = cand2 - zz[ai];
                float dz = __shfl_sync(0xffffffffu, d2, l0);
                if (fabsf(dz) > EPS) {
                    if (lane == l0) zz[ai] = cand2;
                    uu[0] = fmaf(__uint_as_float(g0 << 16),          -dz, uu[0]);
                    uu[4] = fmaf(__uint_as_float(g0 & 0xffff0000u), -dz, uu[4]);
                    uu[1] = fmaf(__uint_as_float(g1 << 16),          -dz, uu[1]);
                    uu[5] = fmaf(__uint_as_float(g1 & 0xffff0000u), -dz, uu[5]);
                    uu[2] = fmaf(__uint_as_float(g2 << 16),          -dz, uu[2]);
                    uu[6] = fmaf(__uint_as_float(g2 & 0xffff0000u), -dz, uu[6]);
                    uu[3] = fmaf(__uint_as_float(g3 << 16),          -dz, uu[3]);
                    uu[7] = fmaf(__uint_as_float(g3 & 0xffff0000u), -dz, uu[7]);
                }
            } while (chg);
        }
        if (!any) break;
    }

    // ---- fp32 residual refresh: u = b - G z (exact, for KKT filter + signs) ----
#pragma unroll
    for (int ai = 0; ai < 8; ++ai)
        uu[ai] = s_b[warp][((ai >> 2) << 7) + ((ai & 3) << 5) + lane];
#pragma unroll
    for (int ai = 0; ai < 8; ++ai) {
        int jbase = ((ai >> 2) << 7) + ((ai & 3) << 5);
        unsigned sup = __ballot_sync(0xffffffffu, zz[ai] != 0.f);
        while (sup) {
            int l0 = __ffs(sup) - 1;
            sup &= sup - 1;
            float zk = __shfl_sync(0xffffffffu, zz[ai], l0);
            const float* gr = g_G + (jbase + l0) * MM + lane;
#pragma unroll
            for (int b = 0; b < 4; ++b) {
                uu[b]     = fmaf(gr[(b << 5)],       -zk, uu[b]);
                uu[b + 4] = fmaf(gr[(b << 5) + 128], -zk, uu[b + 4]);
            }
        }
    }

    // ---- stash residual, build support via KKT filter ----
    // Keep j iff z_j != 0 AND |u_j| near lambda (true support). Sign from residual.
#pragma unroll
    for (int ai = 0; ai < 8; ++ai)
        s_r[warp][((ai >> 2) << 7) + ((ai & 3) << 5) + lane] = uu[ai];

    int cnt = 0;
#pragma unroll
    for (int ai = 0; ai < 8; ++ai) {
        int jbase = ((ai >> 2) << 7) + ((ai & 3) << 5);
        bool keep = (zz[ai] != 0.f) && (fabsf(uu[ai]) > LAMBD - KKT_MARGIN);
        unsigned m = __ballot_sync(0xffffffffu, keep);
        int rank = __popc(m & ((1u << lane) - 1));
        if (keep && (cnt + rank < MAXS)) s_idx[warp][cnt + rank] = jbase + lane;
        cnt += __popc(m);
    }
    int sp = cnt < MAXS ? cnt : MAXS;

    __syncthreads();   // bf16 G dead -> reuse region as refine scratch

    float* A = (float*)Gs + warp * 4096;     // 16KB per warp
    int sld = sp + (sp < MAXS ? 1 : 0);      // sp*sld <= 4096 floats always

    if (sp == 0) {
        if (lane == 0) { out[2 * s] = 0.f; out[2 * s + 1] = -0.0f; }
        return;
    }

    // A = G[S,S] (fp32), rhs = b_S - lambda*sign(u_S)
    for (int r = 0; r < sp; ++r) {
        const float* gr = g_G + s_idx[warp][r] * MM;
        for (int q = lane; q < sp; q += 32) A[r * sld + q] = gr[s_idx[warp][q]];
    }
    for (int t = lane; t < sp; t += 32) {
        int j = s_idx[warp][t];
        s_vec[warp][t] = s_b[warp][j] - copysignf(LAMBD, s_r[warp][j]);
    }
    __syncwarp();

    // Cholesky A = L L^T (lower), warp-synchronous, IEEE-rounded pivots
    for (int k = 0; k < sp; ++k) {
        float dk = A[k * sld + k];
        float piv = __fsqrt_rn(fmaxf(dk, 1e-30f));
        float inv = __frcp_rn(piv);
        for (int r = k + 1 + lane; r < sp; r += 32) A[r * sld + k] *= inv;
        if (lane == 0) A[k * sld + k] = piv;
        __syncwarp();
        for (int r = k + 1 + lane; r < sp; r += 32) {
            float lrk = A[r * sld + k];
            for (int q = k + 1; q <= r; ++q) A[r * sld + q] -= lrk * A[q * sld + k];
        }
        __syncwarp();
    }
    // forward solve L y = rhs
    for (int k = 0; k < sp; ++k) {
        float vk = __fdiv_rn(s_vec[warp][k], A[k * sld + k]);
        if (lane == 0) s_vec[warp][k] = vk;
        for (int r = k + 1 + lane; r < sp; r += 32) s_vec[warp][r] -= A[r * sld + k] * vk;
        __syncwarp();
    }
    // backward solve L^T a = y
    for (int k = sp - 1; k >= 0; --k) {
        float vk = __fdiv_rn(s_vec[warp][k], A[k * sld + k]);
        if (lane == 0) s_vec[warp][k] = vk;
        for (int r = lane; r < k; r += 32) s_vec[warp][r] -= A[k * sld + r] * vk;
        __syncwarp();
    }
    // y = w_S . alpha_S
    float p = 0.f;
    for (int t = lane; t < sp; t += 32) p += w[s_idx[warp][t]] * s_vec[warp][t];
#pragma unroll
    for (int o = 16; o; o >>= 1) p += __shfl_down_sync(0xffffffffu, p, o);
    if (lane == 0) {
        out[2 * s] = p;
        out[2 * s + 1] = -p;
    }
}

// ---------------- launch ----------------
extern "C" void kernel_launch(void* const* d_in, const int* in_sizes, int n_in,
                              void* d_out, int out_size) {
    const float* x = (const float*)d_in[0];   // (1024, 64)
    const float* D = (const float*)d_in[1];   // (64, 256)
    const float* w = (const float*)d_in[2];   // (256,)
    float* out = (float*)d_out;               // (1024, 2)

    cudaFuncSetAttribute(main_kernel, cudaFuncAttributeMaxDynamicSharedMemorySize, CD_SMEM);

    gram_pack_kernel<<<256, 256>>>(D);
    main_kernel<<<128, 256, CD_SMEM>>>(x, D, w, out);
}

// round 12
// speedup vs baseline: 1.6430x; 1.6430x over previous
#include <cuda_runtime.h>
#include <cuda_bf16.h>
#include <cstdint>

// Problem: x (1024,64), D (64,256), w (256). Output (1024,2) fp32.
#define NN 1024
#define MM 256
#define DN 64
#define LAMBD 0.2f
#define EPS 1e-5f
#define KKT_MARGIN 1e-3f
#define MAX_SWEEPS 64
#define MAXS 64

// ---------------- device scratch ----------------
__device__ float    g_G[MM * MM];      // fp32 Gram D^T D, row-major
__device__ unsigned g_Gp[MM * 128];    // packed bf16x2: word[j*128+t] = (G[j][t], G[j][t+128])

// ---------------- K1: G = D^T D, fused bf16x2 pack ----------------
__global__ void gram_pack_kernel(const float* __restrict__ D) {
    __shared__ float Dj[DN];
    __shared__ float row[MM];
    int j = blockIdx.x, k = threadIdx.x;
    if (k < DN) Dj[k] = D[k * MM + j];
    __syncthreads();
    float acc = 0.f;
#pragma unroll 8
    for (int n = 0; n < DN; ++n) acc = fmaf(Dj[n], D[n * MM + k], acc);
    g_G[j * MM + k] = acc;
    row[k] = acc;
    __syncthreads();
    if (k < 128) {
        unsigned u0 = (unsigned)__bfloat16_as_ushort(__float2bfloat16(row[k]));
        unsigned u1 = (unsigned)__bfloat16_as_ushort(__float2bfloat16(row[k + 128]));
        g_Gp[j * 128 + k] = u0 | (u1 << 16);
    }
}

// ---------------- K2: fused b=D^Tx -> CD (rem-loop, PAIRED updates per ballot)
//                  -> fp32 residual refresh -> KKT filter -> warp Cholesky refine ----------------
// 128 blocks x 256 threads. Warp per sample. Lane l owns coords
// j(ai) = ((ai>>2)<<7) + ((ai&3)<<5) + l, ai = 0..7.
// Dynamic smem: 128KB bf16x2 G; after CD reused as 8 x 16KB per-warp Cholesky scratch.
#define CD_SMEM (MM * 128 * 4)

__global__ void __launch_bounds__(256, 1) main_kernel(const float* __restrict__ x,
                                                      const float* __restrict__ D,
                                                      const float* __restrict__ w,
                                                      float* __restrict__ out) {
    extern __shared__ unsigned Gs[];         // 32768 words bf16x2 G, later refine scratch
    __shared__ float s_b[8][MM];             // b per warp
    __shared__ float s_r[8][MM];             // refreshed residual u per warp (KKT + signs)
    __shared__ int   s_idx[8][MAXS];
    __shared__ float s_vec[8][MAXS];

    // cooperative load of packed G
    {
        const uint4* src = (const uint4*)g_Gp;
        uint4* dst = (uint4*)Gs;
        for (int t = threadIdx.x; t < (MM * 128) / 4; t += 256) dst[t] = src[t];
    }

    int warp = threadIdx.x >> 5, lane = threadIdx.x & 31;
    int s = blockIdx.x * 8 + warp;

    // ---- prologue: b = D^T x_s, register accumulators ----
    float x0 = x[s * DN + lane];
    float x1 = x[s * DN + 32 + lane];
    float uu[8], zz[8];
#pragma unroll
    for (int ai = 0; ai < 8; ++ai) { uu[ai] = 0.f; zz[ai] = 0.f; }
#pragma unroll 4
    for (int n = 0; n < 32; ++n) {
        float xs = __shfl_sync(0xffffffffu, x0, n);
        const float* dr = D + n * MM + lane;
#pragma unroll
        for (int ai = 0; ai < 8; ++ai)
            uu[ai] = fmaf(xs, dr[((ai >> 2) << 7) + ((ai & 3) << 5)], uu[ai]);
    }
#pragma unroll 4
    for (int n = 0; n < 32; ++n) {
        float xs = __shfl_sync(0xffffffffu, x1, n);
        const float* dr = D + (n + 32) * MM + lane;
#pragma unroll
        for (int ai = 0; ai < 8; ++ai)
            uu[ai] = fmaf(xs, dr[((ai >> 2) << 7) + ((ai & 3) << 5)], uu[ai]);
    }
#pragma unroll
    for (int ai = 0; ai < 8; ++ai)
        s_b[warp][((ai >> 2) << 7) + ((ai & 3) << 5) + lane] = uu[ai];

    __syncthreads();   // G smem ready

    // ---- CD: rem-loop; per ballot round apply up to TWO updates (2-coord Jacobi
    //      step using ballot-time candidates; coupling |G_jk|~0.12 -> convergent,
    //      residual cross-error cleaned by the immediate re-ballot) ----
    for (int sweep = 0; sweep < MAX_SWEEPS; ++sweep) {
        unsigned any = 0;
#pragma unroll
        for (int ai = 0; ai < 8; ++ai) {
            int jbase = ((ai >> 2) << 7) + ((ai & 3) << 5);
            unsigned rem = 0xffffffffu;
            while (true) {
                float c = uu[ai] + zz[ai];
                float ab = fabsf(c) - LAMBD;
                float cand = ab > 0.f ? copysignf(ab, c) : 0.f;
                float dzl = cand - zz[ai];
                unsigned chg = __ballot_sync(0xffffffffu, fabsf(dzl) > EPS) & rem;
                if (!chg) break;
                any = 1;
                int l0 = __ffs(chg) - 1;
                chg &= chg - 1;
                int l1 = chg ? (__ffs(chg) - 1) : -1;
                rem &= ~(1u << l0);
                float dz0 = __shfl_sync(0xffffffffu, dzl, l0);
                if (lane == l0) zz[ai] = cand;
                const unsigned* gr0 = Gs + ((jbase + l0) << 7) + lane;
                unsigned a0 = gr0[0], a1 = gr0[32], a2 = gr0[64], a3 = gr0[96];
                uu[0] = fmaf(__uint_as_float(a0 << 16),          -dz0, uu[0]);
                uu[4] = fmaf(__uint_as_float(a0 & 0xffff0000u), -dz0, uu[4]);
                uu[1] = fmaf(__uint_as_float(a1 << 16),          -dz0, uu[1]);
                uu[5] = fmaf(__uint_as_float(a1 & 0xffff0000u), -dz0, uu[5]);
                uu[2] = fmaf(__uint_as_float(a2 << 16),          -dz0, uu[2]);
                uu[6] = fmaf(__uint_as_float(a2 & 0xffff0000u), -dz0, uu[6]);
                uu[3] = fmaf(__uint_as_float(a3 << 16),          -dz0, uu[3]);
                uu[7] = fmaf(__uint_as_float(a3 & 0xffff0000u), -dz0, uu[7]);
                if (l1 >= 0) {
                    rem &= ~(1u << l1);
                    float dz1 = __shfl_sync(0xffffffffu, dzl, l1);
                    if (lane == l1) zz[ai] = cand;
                    const unsigned* gr1 = Gs + ((jbase + l1) << 7) + lane;
                    unsigned b0 = gr1[0], b1 = gr1[32], b2 = gr1[64], b3 = gr1[96];
                    uu[0] = fmaf(__uint_as_float(b0 << 16),          -dz1, uu[0]);
                    uu[4] = fmaf(__uint_as_float(b0 & 0xffff0000u), -dz1, uu[4]);
                    uu[1] = fmaf(__uint_as_float(b1 << 16),          -dz1, uu[1]);
                    uu[5] = fmaf(__uint_as_float(b1 & 0xffff0000u), -dz1, uu[5]);
                    uu[2] = fmaf(__uint_as_float(b2 << 16),          -dz1, uu[2]);
                    uu[6] = fmaf(__uint_as_float(b2 & 0xffff0000u), -dz1, uu[6]);
                    uu[3] = fmaf(__uint_as_float(b3 << 16),          -dz1, uu[3]);
                    uu[7] = fmaf(__uint_as_float(b3 & 0xffff0000u), -dz1, uu[7]);
                }
            }
        }
        if (!any) break;
    }

    // ---- fp32 residual refresh: u = b - G z (exact, for KKT filter + signs) ----
#pragma unroll
    for (int ai = 0; ai < 8; ++ai)
        uu[ai] = s_b[warp][((ai >> 2) << 7) + ((ai & 3) << 5) + lane];
#pragma unroll
    for (int ai = 0; ai < 8; ++ai) {
        int jbase = ((ai >> 2) << 7) + ((ai & 3) << 5);
        unsigned sup = __ballot_sync(0xffffffffu, zz[ai] != 0.f);
        while (sup) {
            int l0 = __ffs(sup) - 1;
            sup &= sup - 1;
            float zk = __shfl_sync(0xffffffffu, zz[ai], l0);
            const float* gr = g_G + (jbase + l0) * MM + lane;
#pragma unroll
            for (int b = 0; b < 4; ++b) {
                uu[b]     = fmaf(gr[(b << 5)],       -zk, uu[b]);
                uu[b + 4] = fmaf(gr[(b << 5) + 128], -zk, uu[b + 4]);
            }
        }
    }

    // ---- stash residual, build support via KKT filter ----
    // Keep j iff z_j != 0 AND |u_j| near lambda (true support). Sign from residual.
#pragma unroll
    for (int ai = 0; ai < 8; ++ai)
        s_r[warp][((ai >> 2) << 7) + ((ai & 3) << 5) + lane] = uu[ai];

    int cnt = 0;
#pragma unroll
    for (int ai = 0; ai < 8; ++ai) {
        int jbase = ((ai >> 2) << 7) + ((ai & 3) << 5);
        bool keep = (zz[ai] != 0.f) && (fabsf(uu[ai]) > LAMBD - KKT_MARGIN);
        unsigned m = __ballot_sync(0xffffffffu, keep);
        int rank = __popc(m & ((1u << lane) - 1));
        if (keep && (cnt + rank < MAXS)) s_idx[warp][cnt + rank] = jbase + lane;
        cnt += __popc(m);
    }
    int sp = cnt < MAXS ? cnt : MAXS;

    __syncthreads();   // bf16 G dead -> reuse region as refine scratch

    float* A = (float*)Gs + warp * 4096;     // 16KB per warp
    int sld = sp + (sp < MAXS ? 1 : 0);      // sp*sld <= 4096 floats always

    if (sp == 0) {
        if (lane == 0) { out[2 * s] = 0.f; out[2 * s + 1] = -0.0f; }
        return;
    }

    // A = G[S,S] (fp32), rhs = b_S - lambda*sign(u_S)
    for (int r = 0; r < sp; ++r) {
        const float* gr = g_G + s_idx[warp][r] * MM;
        for (int q = lane; q < sp; q += 32) A[r * sld + q] = gr[s_idx[warp][q]];
    }
    for (int t = lane; t < sp; t += 32) {
        int j = s_idx[warp][t];
        s_vec[warp][t] = s_b[warp][j] - copysignf(LAMBD, s_r[warp][j]);
    }
    __syncwarp();

    // Cholesky A = L L^T (lower), warp-synchronous, IEEE-rounded pivots
    for (int k = 0; k < sp; ++k) {
        float dk = A[k * sld + k];
        float piv = __fsqrt_rn(fmaxf(dk, 1e-30f));
        float inv = __frcp_rn(piv);
        for (int r = k + 1 + lane; r < sp; r += 32) A[r * sld + k] *= inv;
        if (lane == 0) A[k * sld + k] = piv;
        __syncwarp();
        for (int r = k + 1 + lane; r < sp; r += 32) {
            float lrk = A[r * sld + k];
            for (int q = k + 1; q <= r; ++q) A[r * sld + q] -= lrk * A[q * sld + k];
        }
        __syncwarp();
    }
    // forward solve L y = rhs
    for (int k = 0; k < sp; ++k) {
        float vk = __fdiv_rn(s_vec[warp][k], A[k * sld + k]);
        if (lane == 0) s_vec[warp][k] = vk;
        for (int r = k + 1 + lane; r < sp; r += 32) s_vec[warp][r] -= A[r * sld + k] * vk;
        __syncwarp();
    }
    // backward solve L^T a = y
    for (int k = sp - 1; k >= 0; --k) {
        float vk = __fdiv_rn(s_vec[warp][k], A[k * sld + k]);
        if (lane == 0) s_vec[warp][k] = vk;
        for (int r = lane; r < k; r += 32) s_vec[warp][r] -= A[k * sld + r] * vk;
        __syncwarp();
    }
    // y = w_S . alpha_S
    float p = 0.f;
    for (int t = lane; t < sp; t += 32) p += w[s_idx[warp][t]] * s_vec[warp][t];
#pragma unroll
    for (int o = 16; o; o >>= 1) p += __shfl_down_sync(0xffffffffu, p, o);
    if (lane == 0) {
        out[2 * s] = p;
        out[2 * s + 1] = -p;
    }
}

// ---------------- launch ----------------
extern "C" void kernel_launch(void* const* d_in, const int* in_sizes, int n_in,
                              void* d_out, int out_size) {
    const float* x = (const float*)d_in[0];   // (1024, 64)
    const float* D = (const float*)d_in[1];   // (64, 256)
    const float* w = (const float*)d_in[2];   // (256,)
    float* out = (float*)d_out;               // (1024, 2)

    cudaFuncSetAttribute(main_kernel, cudaFuncAttributeMaxDynamicSharedMemorySize, CD_SMEM);

    gram_pack_kernel<<<256, 256>>>(D);
    main_kernel<<<128, 256, CD_SMEM>>>(x, D, w, out);
}